// round 8
// baseline (speedup 1.0000x reference)
#include <cuda_runtime.h>
#include <math.h>
#include <stdint.h>

// Problem constants
#define Bc    2
#define Sc    2048
#define Ec    2048
#define Hc    16
#define HDc   128
#define Mrows 4096     // B*S
#define QKV_N 6144     // 3*E
#define GK    2048     // K dim of both GEMMs

// Scratch (device globals: allocation-free per harness rules)
__device__ float g_qkv[(size_t)Mrows * QKV_N];   // ~100 MB
__device__ float g_attn[(size_t)Mrows * Ec];     // ~33 MB

// ---------------------------------------------------------------------------
// Helpers
// ---------------------------------------------------------------------------
__device__ __forceinline__ uint32_t f2tf32(float x) {
    uint32_t r;
    asm("cvt.rna.tf32.f32 %0, %1;" : "=r"(r) : "f"(x));
    return r;
}
__device__ __forceinline__ uint2 split_tf32(float x) {
    uint32_t hi = f2tf32(x);
    uint32_t lo = f2tf32(x - __uint_as_float(hi));
    return make_uint2(hi, lo);
}
__device__ __forceinline__ void mma8(float* c,
                                     uint32_t a0, uint32_t a1, uint32_t a2, uint32_t a3,
                                     uint32_t b0, uint32_t b1) {
    asm volatile(
        "mma.sync.aligned.m16n8k8.row.col.f32.tf32.tf32.f32 "
        "{%0,%1,%2,%3}, {%4,%5,%6,%7}, {%8,%9}, {%0,%1,%2,%3};"
        : "+f"(c[0]), "+f"(c[1]), "+f"(c[2]), "+f"(c[3])
        : "r"(a0), "r"(a1), "r"(a2), "r"(a3), "r"(b0), "r"(b1));
}

// ---------------------------------------------------------------------------
// 3xTF32 GEMM, 512 threads, warp tile 32x32, DOUBLE-BUFFERED smem with a
// single __syncthreads per K-step so convert/STS overlaps mma across warps.
// C[M,N] = A[M,K] @ B[N,K]^T + bias[N], 128x128 CTA tile, BK=32.
// ---------------------------------------------------------------------------
#define SPAD 36                      // row stride in uint2 (conflict-free)
#define STG_U2 (2 * 128 * SPAD)      // uint2 per stage (As+Bs) = 9216

__global__ __launch_bounds__(512)
void gemm_tf32x3_db(const float* __restrict__ A,
                    const float* __restrict__ Bw,
                    const float* __restrict__ bias,
                    float* __restrict__ C,
                    int Ndim)
{
    extern __shared__ uint2 sm2[];   // 2 stages x (As[128][36] + Bs[128][36])

    const int tid   = threadIdx.x;
    const int lane  = tid & 31;
    const int wid   = tid >> 5;          // 0..15
    const int m_off = (wid & 3) << 5;    // 0,32,64,96
    const int n_off = (wid >> 2) << 5;   // 0,32,64,96
    const int bm    = blockIdx.y << 7;
    const int bn    = blockIdx.x << 7;

    // loader mapping: one row per 4 threads, 8 consecutive k's each
    const int lrow = tid >> 2;           // 0..127
    const int lcol = (tid & 3) << 3;     // 0,8,16,24

    const float* Arow = A  + (size_t)(bm + lrow) * GK + lcol;
    const float* Brow = Bw + (size_t)(bn + lrow) * GK + lcol;

    float c[2][4][4];
#pragma unroll
    for (int mt = 0; mt < 2; mt++)
#pragma unroll
        for (int nt = 0; nt < 4; nt++)
#pragma unroll
            for (int e = 0; e < 4; e++) c[mt][nt][e] = 0.f;

    float4 pa[2], pb[2];

    // convert current regs into stage buffer
    auto conv_store = [&](uint2* stage) {
        uint2* As = stage;
        uint2* Bs = stage + 128 * SPAD;
#pragma unroll
        for (int j = 0; j < 2; j++) {
            float av[4] = {pa[j].x, pa[j].y, pa[j].z, pa[j].w};
            float bv[4] = {pb[j].x, pb[j].y, pb[j].z, pb[j].w};
            uint2 ah[4], bh[4];
#pragma unroll
            for (int e = 0; e < 4; e++) { ah[e] = split_tf32(av[e]); bh[e] = split_tf32(bv[e]); }
            int base = lrow * SPAD + lcol + 4*j;
            *(uint4*)&As[base    ] = make_uint4(ah[0].x, ah[0].y, ah[1].x, ah[1].y);
            *(uint4*)&As[base + 2] = make_uint4(ah[2].x, ah[2].y, ah[3].x, ah[3].y);
            *(uint4*)&Bs[base    ] = make_uint4(bh[0].x, bh[0].y, bh[1].x, bh[1].y);
            *(uint4*)&Bs[base + 2] = make_uint4(bh[2].x, bh[2].y, bh[3].x, bh[3].y);
        }
    };

    // prologue: regs <- slab 0; buf0 <- convert; regs <- slab 1
#pragma unroll
    for (int j = 0; j < 2; j++) {
        pa[j] = *(const float4*)(Arow + 4*j);
        pb[j] = *(const float4*)(Brow + 4*j);
    }
    conv_store(sm2);
#pragma unroll
    for (int j = 0; j < 2; j++) {
        pa[j] = *(const float4*)(Arow + 32 + 4*j);
        pb[j] = *(const float4*)(Brow + 32 + 4*j);
    }
    __syncthreads();

    const int nsteps = GK / 32;   // 64
#pragma unroll 1
    for (int step = 0; step < nsteps; step++) {
        const int s = step & 1;
        uint2* cur = sm2 + s * STG_U2;

        // 1) convert regs (slab step+1) into the other buffer
        if (step + 1 < nsteps) conv_store(sm2 + (s ^ 1) * STG_U2);

        // 2) issue global loads for slab step+2
        if (step + 2 < nsteps) {
            int k0 = (step + 2) * 32;
#pragma unroll
            for (int j = 0; j < 2; j++) {
                pa[j] = *(const float4*)(Arow + k0 + 4*j);
                pb[j] = *(const float4*)(Brow + k0 + 4*j);
            }
        }

        // 3) mma on current buffer
        uint2* As = cur;
        uint2* Bs = cur + 128 * SPAD;
#pragma unroll
        for (int kk = 0; kk < 4; kk++) {
            const int kc = (kk << 3) + (lane & 3);
            uint2 a[2][4];
#pragma unroll
            for (int mt = 0; mt < 2; mt++) {
                int r0 = m_off + mt * 16 + (lane >> 2);
                a[mt][0] = As[r0 * SPAD + kc];
                a[mt][1] = As[(r0 + 8) * SPAD + kc];
                a[mt][2] = As[r0 * SPAD + kc + 4];
                a[mt][3] = As[(r0 + 8) * SPAD + kc + 4];
            }
            uint2 b[4][2];
#pragma unroll
            for (int nt = 0; nt < 4; nt++) {
                int n0 = n_off + nt * 8 + (lane >> 2);
                b[nt][0] = Bs[n0 * SPAD + kc];
                b[nt][1] = Bs[n0 * SPAD + kc + 4];
            }
#pragma unroll
            for (int mt = 0; mt < 2; mt++)
#pragma unroll
                for (int nt = 0; nt < 4; nt++) {
                    mma8(c[mt][nt], a[mt][0].x, a[mt][1].x, a[mt][2].x, a[mt][3].x,
                                    b[nt][0].x, b[nt][1].x);
                    mma8(c[mt][nt], a[mt][0].x, a[mt][1].x, a[mt][2].x, a[mt][3].x,
                                    b[nt][0].y, b[nt][1].y);
                    mma8(c[mt][nt], a[mt][0].y, a[mt][1].y, a[mt][2].y, a[mt][3].y,
                                    b[nt][0].x, b[nt][1].x);
                }
        }

        // 4) one barrier: next-buffer writes done before next iter reads them,
        //    and current buffer fully consumed before it is overwritten.
        __syncthreads();
    }

    // epilogue
#pragma unroll
    for (int mt = 0; mt < 2; mt++) {
        int r0 = bm + m_off + mt * 16 + (lane >> 2);
#pragma unroll
        for (int nt = 0; nt < 4; nt++) {
            int col = bn + n_off + nt * 8 + ((lane & 3) << 1);
            float b0 = bias[col], b1 = bias[col + 1];
            *(float2*)&C[(size_t)r0 * Ndim + col] =
                make_float2(c[mt][nt][0] + b0, c[mt][nt][1] + b1);
            *(float2*)&C[(size_t)(r0 + 8) * Ndim + col] =
                make_float2(c[mt][nt][2] + b0, c[mt][nt][3] + b1);
        }
    }
}

// ---------------------------------------------------------------------------
// Flash attention, fp32 SIMT (proven R1 kernel, 2.34 ms)
// ---------------------------------------------------------------------------
#define SQt 128
#define SKt 64
#define DP  132

__global__ __launch_bounds__(256)
void flash_fp32()
{
    extern __shared__ float smf[];
    float* Qs   = smf;
    float* Ks   = Qs  + SQt*DP;
    float* Vs   = Ks  + SKt*DP;
    float* Ps   = Vs  + SKt*DP;
    float* m_s  = Ps  + SQt*SKt;
    float* l_s  = m_s + SQt;
    float* al_s = l_s + SQt;

    const int tid  = threadIdx.x;
    const int lane = tid & 31, wid = tid >> 5;
    const int ty   = tid >> 4, tx  = tid & 15;
    const int b = blockIdx.z, h = blockIdx.y;
    const int q0 = blockIdx.x << 7;

    const size_t qbase = ((size_t)(b*Sc + q0)) * QKV_N + h*384;

#pragma unroll
    for (int i = 0; i < 16; i++) {
        int idx = tid + (i << 8);
        int r   = idx >> 5;
        int c4  = (idx & 31) << 2;
        *(float4*)&Qs[r*DP + c4] =
            *(const float4*)&g_qkv[qbase + (size_t)r*QKV_N + c4];
    }
    if (tid < SQt) { m_s[tid] = -INFINITY; l_s[tid] = 0.f; }

    float o[8][8];
#pragma unroll
    for (int i = 0; i < 8; i++)
#pragma unroll
        for (int c = 0; c < 8; c++) o[i][c] = 0.f;

    const float scale = 11.3137084989847604f;  // HD**0.5 (reference MULTIPLIES)

    for (int kt = 0; kt < Sc; kt += SKt) {
        __syncthreads();
        const size_t kbase = ((size_t)(b*Sc + kt)) * QKV_N + h*384;
#pragma unroll
        for (int i = 0; i < 8; i++) {
            int idx = tid + (i << 8);
            int r   = idx >> 5;
            int c4  = (idx & 31) << 2;
            *(float4*)&Ks[r*DP + c4] =
                *(const float4*)&g_qkv[kbase + (size_t)r*QKV_N + 128 + c4];
            *(float4*)&Vs[r*DP + c4] =
                *(const float4*)&g_qkv[kbase + (size_t)r*QKV_N + 256 + c4];
        }
        __syncthreads();

        float s[8][4];
#pragma unroll
        for (int i = 0; i < 8; i++)
#pragma unroll
            for (int c = 0; c < 4; c++) s[i][c] = 0.f;

#pragma unroll 8
        for (int d = 0; d < HDc; d += 4) {
            float4 kf[4];
#pragma unroll
            for (int c = 0; c < 4; c++)
                kf[c] = *(const float4*)&Ks[(tx + 16*c)*DP + d];
#pragma unroll
            for (int i = 0; i < 8; i++) {
                float4 qf = *(const float4*)&Qs[(8*ty + i)*DP + d];
#pragma unroll
                for (int c = 0; c < 4; c++)
                    s[i][c] += qf.x*kf[c].x + qf.y*kf[c].y
                             + qf.z*kf[c].z + qf.w*kf[c].w;
            }
        }
#pragma unroll
        for (int i = 0; i < 8; i++)
#pragma unroll
            for (int c = 0; c < 4; c++)
                Ps[(8*ty + i)*SKt + tx + 16*c] = s[i][c] * scale;
        __syncthreads();

#pragma unroll 1
        for (int rr = 0; rr < 16; rr++) {
            int r = wid*16 + rr;
            float s0 = Ps[r*SKt + lane];
            float s1 = Ps[r*SKt + 32 + lane];
            float mx = fmaxf(s0, s1);
#pragma unroll
            for (int off = 16; off > 0; off >>= 1)
                mx = fmaxf(mx, __shfl_xor_sync(0xffffffffu, mx, off));
            float mo = m_s[r];
            float mn = fmaxf(mo, mx);
            float p0 = __expf(s0 - mn);
            float p1 = __expf(s1 - mn);
            float ps = p0 + p1;
#pragma unroll
            for (int off = 16; off > 0; off >>= 1)
                ps += __shfl_xor_sync(0xffffffffu, ps, off);
            Ps[r*SKt + lane]      = p0;
            Ps[r*SKt + 32 + lane] = p1;
            if (lane == 0) {
                float al = (mo == -INFINITY) ? 0.f : __expf(mo - mn);
                al_s[r] = al;
                l_s[r]  = l_s[r]*al + ps;
                m_s[r]  = mn;
            }
        }
        __syncthreads();

        float al[8];
#pragma unroll
        for (int i = 0; i < 8; i++) al[i] = al_s[8*ty + i];
#pragma unroll
        for (int i = 0; i < 8; i++)
#pragma unroll
            for (int c = 0; c < 8; c++) o[i][c] *= al[i];

#pragma unroll 4
        for (int j = 0; j < SKt; j++) {
            float p[8], v[8];
#pragma unroll
            for (int i = 0; i < 8; i++) p[i] = Ps[(8*ty + i)*SKt + j];
#pragma unroll
            for (int c = 0; c < 8; c++) v[c] = Vs[j*DP + tx + 16*c];
#pragma unroll
            for (int i = 0; i < 8; i++)
#pragma unroll
                for (int c = 0; c < 8; c++)
                    o[i][c] += p[i]*v[c];
        }
    }

#pragma unroll
    for (int i = 0; i < 8; i++) {
        int r = 8*ty + i;
        float inv = 1.0f / l_s[r];
        size_t obase = ((size_t)(b*Sc + q0 + r)) * Ec + h*HDc;
#pragma unroll
        for (int c = 0; c < 8; c++)
            g_attn[obase + tx + 16*c] = o[i][c] * inv;
    }
}

// ---------------------------------------------------------------------------
extern "C" void kernel_launch(void* const* d_in, const int* in_sizes, int n_in,
                              void* d_out, int out_size)
{
    const float* query = (const float*)d_in[0];
    const float* Wqkv  = (const float*)d_in[3];
    const float* bqkv  = (const float*)d_in[4];
    const float* Wproj = (const float*)d_in[5];
    const float* bproj = (const float*)d_in[6];
    float* out = (float*)d_out;

    float *qkvp = nullptr, *attnp = nullptr;
    cudaGetSymbolAddress((void**)&qkvp,  g_qkv);
    cudaGetSymbolAddress((void**)&attnp, g_attn);

    const int gemm_smem = 2 * STG_U2 * (int)sizeof(uint2);  // 147456
    cudaFuncSetAttribute(gemm_tf32x3_db,
                         cudaFuncAttributeMaxDynamicSharedMemorySize, gemm_smem);

    // 1) qkv = query @ Wqkv^T + bqkv
    gemm_tf32x3_db<<<dim3(QKV_N/128, Mrows/128), 512, gemm_smem>>>(
        query, Wqkv, bqkv, qkvp, QKV_N);

    // 2) flash attention -> g_attn
    const int fl_smem = (SQt*DP + 2*SKt*DP + SQt*SKt + 3*SQt) * (int)sizeof(float);
    cudaFuncSetAttribute(flash_fp32,
                         cudaFuncAttributeMaxDynamicSharedMemorySize, fl_smem);
    flash_fp32<<<dim3(Sc/128, Hc, Bc), 256, fl_smem>>>();

    // 3) out = attn @ Wproj^T + bproj
    gemm_tf32x3_db<<<dim3(Ec/128, Mrows/128), 512, gemm_smem>>>(
        attnp, Wproj, bproj, out, Ec);
}

// round 9
// speedup vs baseline: 1.0591x; 1.0591x over previous
#include <cuda_runtime.h>
#include <math.h>
#include <stdint.h>

// Problem constants
#define Bc    2
#define Sc    2048
#define Ec    2048
#define Hc    16
#define HDc   128
#define Mrows 4096     // B*S
#define QKV_N 6144     // 3*E
#define GK    2048     // K dim of both GEMMs

// Scratch (device globals: allocation-free per harness rules)
__device__ float g_qkv[(size_t)Mrows * QKV_N];   // ~100 MB
__device__ float g_attn[(size_t)Mrows * Ec];     // ~33 MB

// ---------------------------------------------------------------------------
// Helpers
// ---------------------------------------------------------------------------
__device__ __forceinline__ uint32_t f2tf32(float x) {
    uint32_t r;
    asm("cvt.rna.tf32.f32 %0, %1;" : "=r"(r) : "f"(x));
    return r;
}
__device__ __forceinline__ uint2 split_tf32(float x) {
    uint32_t hi = f2tf32(x);
    uint32_t lo = f2tf32(x - __uint_as_float(hi));
    return make_uint2(hi, lo);
}
__device__ __forceinline__ void mma8(float* c,
                                     uint32_t a0, uint32_t a1, uint32_t a2, uint32_t a3,
                                     uint32_t b0, uint32_t b1) {
    asm volatile(
        "mma.sync.aligned.m16n8k8.row.col.f32.tf32.tf32.f32 "
        "{%0,%1,%2,%3}, {%4,%5,%6,%7}, {%8,%9}, {%0,%1,%2,%3};"
        : "+f"(c[0]), "+f"(c[1]), "+f"(c[2]), "+f"(c[3])
        : "r"(a0), "r"(a1), "r"(a2), "r"(a3), "r"(b0), "r"(b1));
}

// ---------------------------------------------------------------------------
// 3xTF32 tensor-core GEMM (R2 kernel, TERM-MAJOR mma ordering).
// C[M,N] = A[M,K] @ B[N,K]^T + bias[N], 128x128 tile, BK=32, 256 threads,
// warp tile 64x32. The ONLY change vs the 2.16ms R2 kernel: the 48 mmas per
// kk are issued term-major (16 independent hh, then 16 hl, then 16 lh) so
// consecutive asm-volatile mmas never share an accumulator.
// ---------------------------------------------------------------------------
#define BKg 32
#define SPAD 36

__global__ __launch_bounds__(256)
void gemm_tf32x3_tm(const float* __restrict__ A,
                    const float* __restrict__ Bw,
                    const float* __restrict__ bias,
                    float* __restrict__ C,
                    int Ndim)
{
    extern __shared__ uint2 sm2[];
    uint2* As = sm2;                 // [128][SPAD]
    uint2* Bs = sm2 + 128 * SPAD;

    const int tid   = threadIdx.x;
    const int lane  = tid & 31;
    const int wid   = tid >> 5;
    const int m_off = (wid & 1) << 6;
    const int n_off = (wid >> 1) << 5;
    const int bm    = blockIdx.y << 7;
    const int bn    = blockIdx.x << 7;

    const int row_base = tid >> 3;
    const int col4     = (tid & 7) << 2;

    float c[4][4][4];
#pragma unroll
    for (int mt = 0; mt < 4; mt++)
#pragma unroll
        for (int nt = 0; nt < 4; nt++)
#pragma unroll
            for (int e = 0; e < 4; e++) c[mt][nt][e] = 0.f;

    float4 pa[4], pb[4];
#pragma unroll
    for (int i = 0; i < 4; i++) {
        int r = row_base + 32 * i;
        pa[i] = *(const float4*)&A [(size_t)(bm + r) * GK + col4];
        pb[i] = *(const float4*)&Bw[(size_t)(bn + r) * GK + col4];
    }

    const int nsteps = GK / BKg;
#pragma unroll 1
    for (int step = 0; step < nsteps; step++) {
        __syncthreads();
#pragma unroll
        for (int i = 0; i < 4; i++) {
            int r = row_base + 32 * i;
            float av[4] = {pa[i].x, pa[i].y, pa[i].z, pa[i].w};
            float bv[4] = {pb[i].x, pb[i].y, pb[i].z, pb[i].w};
            uint2 ah[4], bh[4];
#pragma unroll
            for (int j = 0; j < 4; j++) { ah[j] = split_tf32(av[j]); bh[j] = split_tf32(bv[j]); }
            *(uint4*)&As[r * SPAD + col4    ] = make_uint4(ah[0].x, ah[0].y, ah[1].x, ah[1].y);
            *(uint4*)&As[r * SPAD + col4 + 2] = make_uint4(ah[2].x, ah[2].y, ah[3].x, ah[3].y);
            *(uint4*)&Bs[r * SPAD + col4    ] = make_uint4(bh[0].x, bh[0].y, bh[1].x, bh[1].y);
            *(uint4*)&Bs[r * SPAD + col4 + 2] = make_uint4(bh[2].x, bh[2].y, bh[3].x, bh[3].y);
        }
        __syncthreads();

        if (step + 1 < nsteps) {
            int k0 = (step + 1) * BKg;
#pragma unroll
            for (int i = 0; i < 4; i++) {
                int r = row_base + 32 * i;
                pa[i] = *(const float4*)&A [(size_t)(bm + r) * GK + k0 + col4];
                pb[i] = *(const float4*)&Bw[(size_t)(bn + r) * GK + k0 + col4];
            }
        }

#pragma unroll
        for (int kk = 0; kk < 4; kk++) {
            const int kc = (kk << 3) + (lane & 3);
            uint2 a[4][4];
#pragma unroll
            for (int mt = 0; mt < 4; mt++) {
                int r0 = m_off + mt * 16 + (lane >> 2);
                a[mt][0] = As[r0 * SPAD + kc];
                a[mt][1] = As[(r0 + 8) * SPAD + kc];
                a[mt][2] = As[r0 * SPAD + kc + 4];
                a[mt][3] = As[(r0 + 8) * SPAD + kc + 4];
            }
            uint2 b[4][2];
#pragma unroll
            for (int nt = 0; nt < 4; nt++) {
                int n0 = n_off + nt * 8 + (lane >> 2);
                b[nt][0] = Bs[n0 * SPAD + kc];
                b[nt][1] = Bs[n0 * SPAD + kc + 4];
            }
            // ---- TERM-MAJOR: 16 independent mmas per term ----
#pragma unroll
            for (int mt = 0; mt < 4; mt++)
#pragma unroll
                for (int nt = 0; nt < 4; nt++)
                    mma8(c[mt][nt], a[mt][0].x, a[mt][1].x, a[mt][2].x, a[mt][3].x,
                                    b[nt][0].x, b[nt][1].x);
#pragma unroll
            for (int mt = 0; mt < 4; mt++)
#pragma unroll
                for (int nt = 0; nt < 4; nt++)
                    mma8(c[mt][nt], a[mt][0].x, a[mt][1].x, a[mt][2].x, a[mt][3].x,
                                    b[nt][0].y, b[nt][1].y);
#pragma unroll
            for (int mt = 0; mt < 4; mt++)
#pragma unroll
                for (int nt = 0; nt < 4; nt++)
                    mma8(c[mt][nt], a[mt][0].y, a[mt][1].y, a[mt][2].y, a[mt][3].y,
                                    b[nt][0].x, b[nt][1].x);
        }
    }

#pragma unroll
    for (int mt = 0; mt < 4; mt++) {
        int r0 = bm + m_off + mt * 16 + (lane >> 2);
#pragma unroll
        for (int nt = 0; nt < 4; nt++) {
            int col = bn + n_off + nt * 8 + ((lane & 3) << 1);
            float b0 = bias[col], b1 = bias[col + 1];
            *(float2*)&C[(size_t)r0 * Ndim + col] =
                make_float2(c[mt][nt][0] + b0, c[mt][nt][1] + b1);
            *(float2*)&C[(size_t)(r0 + 8) * Ndim + col] =
                make_float2(c[mt][nt][2] + b0, c[mt][nt][3] + b1);
        }
    }
}

// ---------------------------------------------------------------------------
// Flash attention, fp32 SIMT (proven R1 kernel, 2.34 ms)
// ---------------------------------------------------------------------------
#define SQt 128
#define SKt 64
#define DP  132

__global__ __launch_bounds__(256)
void flash_fp32()
{
    extern __shared__ float smf[];
    float* Qs   = smf;
    float* Ks   = Qs  + SQt*DP;
    float* Vs   = Ks  + SKt*DP;
    float* Ps   = Vs  + SKt*DP;
    float* m_s  = Ps  + SQt*SKt;
    float* l_s  = m_s + SQt;
    float* al_s = l_s + SQt;

    const int tid  = threadIdx.x;
    const int lane = tid & 31, wid = tid >> 5;
    const int ty   = tid >> 4, tx  = tid & 15;
    const int b = blockIdx.z, h = blockIdx.y;
    const int q0 = blockIdx.x << 7;

    const size_t qbase = ((size_t)(b*Sc + q0)) * QKV_N + h*384;

#pragma unroll
    for (int i = 0; i < 16; i++) {
        int idx = tid + (i << 8);
        int r   = idx >> 5;
        int c4  = (idx & 31) << 2;
        *(float4*)&Qs[r*DP + c4] =
            *(const float4*)&g_qkv[qbase + (size_t)r*QKV_N + c4];
    }
    if (tid < SQt) { m_s[tid] = -INFINITY; l_s[tid] = 0.f; }

    float o[8][8];
#pragma unroll
    for (int i = 0; i < 8; i++)
#pragma unroll
        for (int c = 0; c < 8; c++) o[i][c] = 0.f;

    const float scale = 11.3137084989847604f;  // HD**0.5 (reference MULTIPLIES)

    for (int kt = 0; kt < Sc; kt += SKt) {
        __syncthreads();
        const size_t kbase = ((size_t)(b*Sc + kt)) * QKV_N + h*384;
#pragma unroll
        for (int i = 0; i < 8; i++) {
            int idx = tid + (i << 8);
            int r   = idx >> 5;
            int c4  = (idx & 31) << 2;
            *(float4*)&Ks[r*DP + c4] =
                *(const float4*)&g_qkv[kbase + (size_t)r*QKV_N + 128 + c4];
            *(float4*)&Vs[r*DP + c4] =
                *(const float4*)&g_qkv[kbase + (size_t)r*QKV_N + 256 + c4];
        }
        __syncthreads();

        float s[8][4];
#pragma unroll
        for (int i = 0; i < 8; i++)
#pragma unroll
            for (int c = 0; c < 4; c++) s[i][c] = 0.f;

#pragma unroll 8
        for (int d = 0; d < HDc; d += 4) {
            float4 kf[4];
#pragma unroll
            for (int c = 0; c < 4; c++)
                kf[c] = *(const float4*)&Ks[(tx + 16*c)*DP + d];
#pragma unroll
            for (int i = 0; i < 8; i++) {
                float4 qf = *(const float4*)&Qs[(8*ty + i)*DP + d];
#pragma unroll
                for (int c = 0; c < 4; c++)
                    s[i][c] += qf.x*kf[c].x + qf.y*kf[c].y
                             + qf.z*kf[c].z + qf.w*kf[c].w;
            }
        }
#pragma unroll
        for (int i = 0; i < 8; i++)
#pragma unroll
            for (int c = 0; c < 4; c++)
                Ps[(8*ty + i)*SKt + tx + 16*c] = s[i][c] * scale;
        __syncthreads();

#pragma unroll 1
        for (int rr = 0; rr < 16; rr++) {
            int r = wid*16 + rr;
            float s0 = Ps[r*SKt + lane];
            float s1 = Ps[r*SKt + 32 + lane];
            float mx = fmaxf(s0, s1);
#pragma unroll
            for (int off = 16; off > 0; off >>= 1)
                mx = fmaxf(mx, __shfl_xor_sync(0xffffffffu, mx, off));
            float mo = m_s[r];
            float mn = fmaxf(mo, mx);
            float p0 = __expf(s0 - mn);
            float p1 = __expf(s1 - mn);
            float ps = p0 + p1;
#pragma unroll
            for (int off = 16; off > 0; off >>= 1)
                ps += __shfl_xor_sync(0xffffffffu, ps, off);
            Ps[r*SKt + lane]      = p0;
            Ps[r*SKt + 32 + lane] = p1;
            if (lane == 0) {
                float al = (mo == -INFINITY) ? 0.f : __expf(mo - mn);
                al_s[r] = al;
                l_s[r]  = l_s[r]*al + ps;
                m_s[r]  = mn;
            }
        }
        __syncthreads();

        float al[8];
#pragma unroll
        for (int i = 0; i < 8; i++) al[i] = al_s[8*ty + i];
#pragma unroll
        for (int i = 0; i < 8; i++)
#pragma unroll
            for (int c = 0; c < 8; c++) o[i][c] *= al[i];

#pragma unroll 4
        for (int j = 0; j < SKt; j++) {
            float p[8], v[8];
#pragma unroll
            for (int i = 0; i < 8; i++) p[i] = Ps[(8*ty + i)*SKt + j];
#pragma unroll
            for (int c = 0; c < 8; c++) v[c] = Vs[j*DP + tx + 16*c];
#pragma unroll
            for (int i = 0; i < 8; i++)
#pragma unroll
                for (int c = 0; c < 8; c++)
                    o[i][c] += p[i]*v[c];
        }
    }

#pragma unroll
    for (int i = 0; i < 8; i++) {
        int r = 8*ty + i;
        float inv = 1.0f / l_s[r];
        size_t obase = ((size_t)(b*Sc + q0 + r)) * Ec + h*HDc;
#pragma unroll
        for (int c = 0; c < 8; c++)
            g_attn[obase + tx + 16*c] = o[i][c] * inv;
    }
}

// ---------------------------------------------------------------------------
extern "C" void kernel_launch(void* const* d_in, const int* in_sizes, int n_in,
                              void* d_out, int out_size)
{
    const float* query = (const float*)d_in[0];
    const float* Wqkv  = (const float*)d_in[3];
    const float* bqkv  = (const float*)d_in[4];
    const float* Wproj = (const float*)d_in[5];
    const float* bproj = (const float*)d_in[6];
    float* out = (float*)d_out;

    float *qkvp = nullptr, *attnp = nullptr;
    cudaGetSymbolAddress((void**)&qkvp,  g_qkv);
    cudaGetSymbolAddress((void**)&attnp, g_attn);

    const int gemm_smem = 2 * 128 * SPAD * (int)sizeof(uint2);  // 73728
    cudaFuncSetAttribute(gemm_tf32x3_tm,
                         cudaFuncAttributeMaxDynamicSharedMemorySize, gemm_smem);

    // 1) qkv = query @ Wqkv^T + bqkv
    gemm_tf32x3_tm<<<dim3(QKV_N/128, Mrows/128), 256, gemm_smem>>>(
        query, Wqkv, bqkv, qkvp, QKV_N);

    // 2) flash attention -> g_attn
    const int fl_smem = (SQt*DP + 2*SKt*DP + SQt*SKt + 3*SQt) * (int)sizeof(float);
    cudaFuncSetAttribute(flash_fp32,
                         cudaFuncAttributeMaxDynamicSharedMemorySize, fl_smem);
    flash_fp32<<<dim3(Sc/128, Hc, Bc), 256, fl_smem>>>();

    // 3) out = attn @ Wproj^T + bproj
    gemm_tf32x3_tm<<<dim3(Ec/128, Mrows/128), 256, gemm_smem>>>(
        attnp, Wproj, bproj, out, Ec);
}